// round 10
// baseline (speedup 1.0000x reference)
#include <cuda_runtime.h>
#include <cuda_fp16.h>
#include <cstdint>

#define Bb 2
#define Ss 4096
#define Dd 512
#define Hh 8
#define Ee 64
#define MR (Bb*Ss)          /* 8192 */
#define NQKV (3*Hh*Ee)      /* 1536 */
#define BH (Bb*Hh)          /* 16 */

// ---------------- scratch (device globals; no allocations allowed) ----------
__device__ __half g_xa[MR*Dd];                // fp16(x)
__device__ __half g_wct[NQKV*Dd];             // fp16 QKV W^T [n][k]
__device__ float g_bcat[NQKV];
__device__ float g_bsum[Dd];
__device__ __half g_wot[Dd*Dd];               // fp16 wo^T [n][k]
__device__ __half g_w1t[Dd*Dd];               // fp16 w1^T
__device__ __half g_w2t[Dd*Dd];               // fp16 w2^T
__device__ __half g_q[BH*Ss*Ee];              // fp16, q pre-scaled
__device__ __half g_k[BH*Ss*Ee];              // fp16
__device__ __half g_vt[BH*Ee*Ss];             // fp16, [bh][e][s]
__device__ __half g_ctx[MR*Dd];               // fp16 ctx [B*S, H*E]
__device__ __half g_ya[MR*Dd];                // fp16 y
__device__ __half g_ha[MR*Dd];                // fp16 hidden

// ---------------- helpers ----------------------------------------------------
__device__ __forceinline__ uint32_t smem_u32(const void* p){
    uint32_t a;
    asm("{ .reg .u64 t; cvta.to.shared.u64 t, %1; cvt.u32.u64 %0, t; }" : "=r"(a) : "l"(p));
    return a;
}
#define LDSM4(r, a) asm volatile( \
    "ldmatrix.sync.aligned.m8n8.x4.shared.b16 {%0,%1,%2,%3}, [%4];" \
    : "=r"((r)[0]), "=r"((r)[1]), "=r"((r)[2]), "=r"((r)[3]) : "r"(a))
#define MMAF16(c, a0,a1,a2,a3, b0,b1) asm volatile( \
    "mma.sync.aligned.m16n8k16.row.col.f32.f16.f16.f32 " \
    "{%0,%1,%2,%3}, {%4,%5,%6,%7}, {%8,%9}, {%0,%1,%2,%3};" \
    : "+f"((c)[0]), "+f"((c)[1]), "+f"((c)[2]), "+f"((c)[3]) \
    : "r"(a0), "r"(a1), "r"(a2), "r"(a3), "r"(b0), "r"(b1))
#define CP16(dst, src) asm volatile( \
    "cp.async.cg.shared.global [%0], [%1], 16;" :: "r"(dst), "l"(src))
#define CP_COMMIT() asm volatile("cp.async.commit_group;" ::: "memory")

// pack two fp32 -> fp16x2 (hi -> upper half, lo -> lower half)
__device__ __forceinline__ uint32_t pack_f16x2(float hi, float lo){
    uint32_t d;
    asm("cvt.rn.f16x2.f32 %0, %1, %2;" : "=r"(d) : "f"(hi), "f"(lo));
    return d;
}

// ---------------- prep kernels -----------------------------------------------
__global__ void split_x_kernel(const float* __restrict__ x)
{
    int i = blockIdx.x*256 + threadIdx.x;
    if (i >= MR*Dd) return;
    g_xa[i] = __float2half_rn(x[i]);
}

__global__ void pack_wqkv_kernel(const float* __restrict__ wq, const float* __restrict__ wk,
                                 const float* __restrict__ wv, const float* __restrict__ bq,
                                 const float* __restrict__ bk, const float* __restrict__ bv)
{
    int i = blockIdx.x*256 + threadIdx.x;
    if (i < NQKV*Dd) {
        int n = i >> 9, k = i & 511;
        int proj = n >> 9, hc = n & 511, h = hc >> 6, e = hc & 63;
        const float* w = (proj==0) ? wq : (proj==1 ? wk : wv);
        g_wct[i] = __float2half_rn(w[(h*Dd + k)*Ee + e]);
    }
    if (i < NQKV) {
        int proj = i >> 9, hc = i & 511;
        const float* bb = (proj==0) ? bq : (proj==1 ? bk : bv);
        g_bcat[i] = bb[hc];
    }
}

__global__ void wtrans_kernel(const float* __restrict__ W, __half* __restrict__ Tt)
{
    int i = blockIdx.x*256 + threadIdx.x;
    if (i >= Dd*Dd) return;
    int n = i >> 9, k = i & 511;
    Tt[i] = __float2half_rn(W[k*Dd + n]);
}

__global__ void bsum_kernel(const float* __restrict__ bo)
{
    int d = blockIdx.x*256 + threadIdx.x;
    if (d < Dd) {
        float s = 0.f;
        #pragma unroll
        for (int h = 0; h < Hh; h++) s += bo[h*Dd + d];
        g_bsum[d] = s;
    }
}

// ---------------- fp16 single-pass tensor GEMM -------------------------------
// C[M,N] = A[M,K] @ Bt^T (Bt is [N][K] row-major, fp16).
// mode 0: fp32 out (+bias,+relu); mode 1: fp16 out; mode 2: QKV scatter.
#define GP 80                   /* 32 fp16 + 16B pad; conflict-free ldmatrix */
#define GS_B 10240
#define GS_SZ 20480
#define G_SMEM (2*GS_SZ)        /* 40960 B */

__global__ __launch_bounds__(256, 2) void gemm_f16_kernel(
    const __half* __restrict__ A, const __half* __restrict__ Bt,
    const float* __restrict__ bias,
    float* __restrict__ C, __half* __restrict__ Ct,
    int M, int N, int K, int mode, int relu)
{
    extern __shared__ char sm[];
    uint32_t sb = smem_u32(sm);
    int t = threadIdx.x, wid = t >> 5, lane = t & 31;
    int mwarp = wid >> 1, nwarp = wid & 1;
    int n0 = blockIdx.x*128, m0 = blockIdx.y*128;
    int l7 = lane & 7;
    int a_blk8 = ((lane >> 3) & 1)*8, a_cofs = ((lane >> 4) & 1)*16;
    int b_blk8 = ((lane >> 4) & 1)*8, b_cofs = ((lane >> 3) & 1)*16;

    const char* pA = (const char*)A;
    const char* pB = (const char*)Bt;

    float acc[2][8][4];
    #pragma unroll
    for (int a = 0; a < 2; a++)
        #pragma unroll
        for (int b = 0; b < 8; b++)
            #pragma unroll
            for (int c = 0; c < 4; c++) acc[a][b][c] = 0.f;

    int nk = K >> 5;

    auto stage = [&](int kb, int buf){
        uint32_t db = sb + (uint32_t)buf*GS_SZ;
        #pragma unroll
        for (int j = 0; j < 2; j++) {
            int idx = t + j*256, r = idx >> 2, u = idx & 3;
            uint32_t d = db + r*GP + u*16;
            CP16(d,        pA + ((size_t)(m0 + r)*K + kb*32 + u*8)*2);
            CP16(d + GS_B, pB + ((size_t)(n0 + r)*K + kb*32 + u*8)*2);
        }
    };

    stage(0, 0); CP_COMMIT();
    stage(1, 1); CP_COMMIT();

    for (int kb = 0; kb < nk; kb++) {
        if (kb < nk - 1) asm volatile("cp.async.wait_group 1;" ::: "memory");
        else             asm volatile("cp.async.wait_group 0;" ::: "memory");
        __syncthreads();
        uint32_t s0 = sb + (uint32_t)(kb & 1)*GS_SZ;

        #pragma unroll
        for (int es = 0; es < 2; es++) {
            uint32_t af[2][4];
            #pragma unroll
            for (int mf = 0; mf < 2; mf++)
                LDSM4(af[mf], s0 + (mwarp*32 + mf*16 + l7 + a_blk8)*GP
                              + es*32 + a_cofs);
            #pragma unroll
            for (int nb = 0; nb < 4; nb++) {
                uint32_t bf4[4];
                LDSM4(bf4, s0 + GS_B + (nwarp*64 + nb*16 + l7 + b_blk8)*GP
                           + es*32 + b_cofs);
                #pragma unroll
                for (int mf = 0; mf < 2; mf++) {
                    MMAF16(acc[mf][2*nb],   af[mf][0],af[mf][1],af[mf][2],af[mf][3], bf4[0], bf4[1]);
                    MMAF16(acc[mf][2*nb+1], af[mf][0],af[mf][1],af[mf][2],af[mf][3], bf4[2], bf4[3]);
                }
            }
        }
        __syncthreads();
        if (kb + 2 < nk) { stage(kb + 2, kb & 1); CP_COMMIT(); }
    }

    // ---- epilogue ----
    #pragma unroll
    for (int mf = 0; mf < 2; mf++) {
        #pragma unroll
        for (int f = 0; f < 8; f++) {
            int c = n0 + nwarp*64 + (f >> 1)*16 + (f & 1)*8 + 2*(lane & 3);
            float b0 = bias[c], b1 = bias[c + 1];
            int r0 = m0 + mwarp*32 + mf*16 + (lane >> 2);
            #pragma unroll
            for (int half = 0; half < 2; half++) {
                int r = r0 + half*8;
                float v0 = acc[mf][f][2*half]     + b0;
                float v1 = acc[mf][f][2*half + 1] + b1;
                if (relu) { v0 = fmaxf(v0, 0.f); v1 = fmaxf(v1, 0.f); }
                if (mode == 0) {
                    *(float2*)&C[(size_t)r*N + c] = make_float2(v0, v1);
                } else if (mode == 1) {
                    ((uint32_t*)Ct)[((size_t)r*N + c) >> 1] = pack_f16x2(v1, v0);
                } else {
                    int n = c;
                    int proj = n >> 9, h = (n >> 6) & 7, e = n & 63;
                    int bh = (r >> 12)*Hh + h;
                    int s = r & 4095;
                    if (proj == 0) { v0 *= 0.125f; v1 *= 0.125f; }
                    if (proj < 2) {
                        __half* dst = (proj ? g_k : g_q);
                        ((uint32_t*)dst)[(((size_t)bh*Ss + s)*Ee + e) >> 1] =
                            pack_f16x2(v1, v0);
                    } else {
                        g_vt[((size_t)bh*Ee + e)*Ss + s]     = __float2half_rn(v0);
                        g_vt[((size_t)bh*Ee + e + 1)*Ss + s] = __float2half_rn(v1);
                    }
                }
            }
        }
    }
}

// ---------------- fp16 single-pass flash attention ---------------------------
// CTA = 128 queries of one (b,h); 8 warps x 16 q-rows; 64-key tiles; occ 2.
#define QK_PITCH 144            /* 64 fp16 = 128 B + 16 pad */
#define V_PITCH  144
#define ST_K 0
#define ST_V 9216
#define ST_SZ 18432
#define ATT_SMEM (2*ST_SZ)      /* 36864 B */

__device__ __forceinline__ void att_stage(
    uint32_t sbase, const __half* kp, const __half* vp,
    size_t bh, int k0, int t)
{
    const char* sk = (const char*)(kp + (bh*Ss + k0)*Ee);
    const char* sv = (const char*)(vp + bh*(size_t)Ee*Ss + k0);
    #pragma unroll
    for (int j = 0; j < 2; j++) {
        int idx = t + j*256, r = idx >> 3, u = idx & 7;
        CP16(sbase + ST_K + r*QK_PITCH + u*16, sk + (size_t)r*128 + u*16);
        CP16(sbase + ST_V + r*V_PITCH + u*16,  sv + (size_t)r*(Ss*2) + u*16);
    }
}

__global__ __launch_bounds__(256, 2) void attn_f16_kernel(
    const __half* __restrict__ qp, const __half* __restrict__ kp,
    const __half* __restrict__ vp, __half* __restrict__ ctx)
{
    extern __shared__ char smem[];
    uint32_t sb = smem_u32(smem);
    int t = threadIdx.x, wid = t >> 5, lane = t & 31;
    int g = lane >> 2, tg = lane & 3;
    size_t bh = blockIdx.y;
    int q0 = blockIdx.x * 128;

    // ---- prologue: stage Q fp16 tile (128 rows x 128 B = full buffer 0) ----
    {
        const char* sq = (const char*)(qp + (bh*Ss + q0)*Ee);
        #pragma unroll
        for (int j = 0; j < 4; j++) {
            int idx = t + j*256, r = idx >> 3, u = idx & 7;
            CP16(sb + r*QK_PITCH + u*16, sq + (size_t)r*128 + u*16);
        }
        CP_COMMIT();
        asm volatile("cp.async.wait_group 0;" ::: "memory");
        __syncthreads();
    }
    uint32_t qf[4][4];
    {
        int arow = wid*16 + (lane & 7) + ((lane >> 3) & 1)*8;
        int acol = ((lane >> 4) & 1)*16;
        #pragma unroll
        for (int es = 0; es < 4; es++)
            LDSM4(qf[es], sb + arow*QK_PITCH + es*32 + acol);
    }
    __syncthreads();

    att_stage(sb,         kp, vp, bh, 0,  t); CP_COMMIT();
    att_stage(sb + ST_SZ, kp, vp, bh, 64, t); CP_COMMIT();

    float o[8][4];
    #pragma unroll
    for (int i = 0; i < 8; i++)
        #pragma unroll
        for (int j = 0; j < 4; j++) o[i][j] = 0.f;
    float rs_lo = 0.f, rs_hi = 0.f;

    int l7 = lane & 7, blkr = ((lane >> 4) & 1)*8, blkc = ((lane >> 3) & 1)*16;

    for (int kt = 0; kt < 64; kt++) {
        if (kt < 63) asm volatile("cp.async.wait_group 1;" ::: "memory");
        else         asm volatile("cp.async.wait_group 0;" ::: "memory");
        __syncthreads();
        uint32_t sof = sb + (uint32_t)(kt & 1)*ST_SZ;

        // ---- S = Q K^T (fp16 single-pass): 4 e-ksteps x 4 key16-tiles ------
        float s[8][4];
        #pragma unroll
        for (int i = 0; i < 8; i++)
            #pragma unroll
            for (int j = 0; j < 4; j++) s[i][j] = 0.f;

        #pragma unroll
        for (int es = 0; es < 4; es++) {
            #pragma unroll
            for (int kg2 = 0; kg2 < 4; kg2++) {
                uint32_t kb[4];
                LDSM4(kb, sof + ST_K + (kg2*16 + blkr + l7)*QK_PITCH
                          + es*32 + blkc);
                MMAF16(s[2*kg2],   qf[es][0],qf[es][1],qf[es][2],qf[es][3], kb[0], kb[1]);
                MMAF16(s[2*kg2+1], qf[es][0],qf[es][1],qf[es][2],qf[es][3], kb[2], kb[3]);
            }
        }

        // ---- fused softmax + PV (fp16 single-pass) -------------------------
        #pragma unroll
        for (int ks = 0; ks < 4; ks++) {
            float p0 = __expf(s[2*ks][0]),   p1 = __expf(s[2*ks][1]);
            float p2 = __expf(s[2*ks][2]),   p3 = __expf(s[2*ks][3]);
            float p4 = __expf(s[2*ks+1][0]), p5 = __expf(s[2*ks+1][1]);
            float p6 = __expf(s[2*ks+1][2]), p7 = __expf(s[2*ks+1][3]);
            rs_lo += (p0 + p1) + (p4 + p5);
            rs_hi += (p2 + p3) + (p6 + p7);
            uint32_t a0 = pack_f16x2(p1, p0);
            uint32_t a1 = pack_f16x2(p3, p2);
            uint32_t a2 = pack_f16x2(p5, p4);
            uint32_t a3 = pack_f16x2(p7, p6);

            #pragma unroll
            for (int eg2 = 0; eg2 < 4; eg2++) {
                uint32_t vb[4];
                LDSM4(vb, sof + ST_V + (eg2*16 + blkr + l7)*V_PITCH
                          + ks*32 + blkc);
                MMAF16(o[2*eg2],   a0, a1, a2, a3, vb[0], vb[1]);
                MMAF16(o[2*eg2+1], a0, a1, a2, a3, vb[2], vb[3]);
            }
        }
        __syncthreads();
        if (kt + 2 < 64) {
            att_stage(sb + (uint32_t)(kt & 1)*ST_SZ, kp, vp, bh, (kt + 2)*64, t);
            CP_COMMIT();
        }
    }

    // ---- normalize + write ctx as fp16 pairs -------------------------------
    rs_lo += __shfl_xor_sync(0xffffffffu, rs_lo, 1);
    rs_lo += __shfl_xor_sync(0xffffffffu, rs_lo, 2);
    rs_hi += __shfl_xor_sync(0xffffffffu, rs_hi, 1);
    rs_hi += __shfl_xor_sync(0xffffffffu, rs_hi, 2);
    float inv_lo = 1.0f / rs_lo, inv_hi = 1.0f / rs_hi;

    int b = (int)(bh >> 3), h = (int)(bh & 7);
    int row0 = q0 + wid*16 + g;
    #pragma unroll
    for (int half = 0; half < 2; half++) {
        int row = row0 + half*8;
        float inv = half ? inv_hi : inv_lo;
        size_t base = ((size_t)b*Ss + row)*Dd + h*Ee;
        #pragma unroll
        for (int j = 0; j < 8; j++) {
            float v0 = o[j][2*half]     * inv;
            float v1 = o[j][2*half + 1] * inv;
            ((uint32_t*)ctx)[(base + j*8 + 2*tg) >> 1] = pack_f16x2(v1, v0);
        }
    }
}

// ---------------- launcher --------------------------------------------------
extern "C" void kernel_launch(void* const* d_in, const int* in_sizes, int n_in,
                              void* d_out, int out_size)
{
    const float* x  = (const float*)d_in[0];
    const float* wq = (const float*)d_in[1];
    const float* bq = (const float*)d_in[2];
    const float* wk = (const float*)d_in[3];
    const float* bk = (const float*)d_in[4];
    const float* wv = (const float*)d_in[5];
    const float* bv = (const float*)d_in[6];
    const float* wo = (const float*)d_in[7];
    const float* bo = (const float*)d_in[8];
    const float* w1 = (const float*)d_in[9];
    const float* b1 = (const float*)d_in[10];
    const float* w2 = (const float*)d_in[11];
    const float* b2 = (const float*)d_in[12];
    float* out = (float*)d_out;

    __half *p_xa, *p_wct, *p_wot, *p_w1t, *p_w2t;
    __half *p_q, *p_k, *p_vt, *p_ctx, *p_ya, *p_ha;
    float *p_bcat, *p_bsum;
    cudaGetSymbolAddress((void**)&p_xa,   g_xa);
    cudaGetSymbolAddress((void**)&p_wct,  g_wct);
    cudaGetSymbolAddress((void**)&p_bcat, g_bcat);
    cudaGetSymbolAddress((void**)&p_bsum, g_bsum);
    cudaGetSymbolAddress((void**)&p_wot,  g_wot);
    cudaGetSymbolAddress((void**)&p_w1t,  g_w1t);
    cudaGetSymbolAddress((void**)&p_w2t,  g_w2t);
    cudaGetSymbolAddress((void**)&p_q,    g_q);
    cudaGetSymbolAddress((void**)&p_k,    g_k);
    cudaGetSymbolAddress((void**)&p_vt,   g_vt);
    cudaGetSymbolAddress((void**)&p_ctx,  g_ctx);
    cudaGetSymbolAddress((void**)&p_ya,   g_ya);
    cudaGetSymbolAddress((void**)&p_ha,   g_ha);

    cudaFuncSetAttribute(attn_f16_kernel,
        cudaFuncAttributeMaxDynamicSharedMemorySize, ATT_SMEM);
    cudaFuncSetAttribute(gemm_f16_kernel,
        cudaFuncAttributeMaxDynamicSharedMemorySize, G_SMEM);

    // prep
    split_x_kernel<<<(MR*Dd + 255)/256, 256>>>(x);
    pack_wqkv_kernel<<<(NQKV*Dd + 255)/256, 256>>>(wq, wk, wv, bq, bk, bv);
    wtrans_kernel<<<(Dd*Dd + 255)/256, 256>>>(wo, p_wot);
    wtrans_kernel<<<(Dd*Dd + 255)/256, 256>>>(w1, p_w1t);
    wtrans_kernel<<<(Dd*Dd + 255)/256, 256>>>(w2, p_w2t);
    bsum_kernel<<<2, 256>>>(bo);

    // QKV projection (fp16, mode 2: scatter to q/k/vt)
    gemm_f16_kernel<<<dim3(NQKV/128, MR/128), 256, G_SMEM>>>(
        p_xa, p_wct, p_bcat, nullptr, nullptr, MR, NQKV, Dd, 2, 0);

    // fp16 attention (writes ctx fp16 in [B*S, H*E])
    attn_f16_kernel<<<dim3(Ss/128, BH), 256, ATT_SMEM>>>(
        p_q, p_k, p_vt, p_ctx);

    // output projection (mode 1 -> fp16 y)
    gemm_f16_kernel<<<dim3(Dd/128, MR/128), 256, G_SMEM>>>(
        p_ctx, p_wot, p_bsum, nullptr, p_ya, MR, Dd, Dd, 1, 0);

    // MLP layer 1 + ReLU (mode 1 -> fp16 hidden)
    gemm_f16_kernel<<<dim3(Dd/128, MR/128), 256, G_SMEM>>>(
        p_ya, p_w1t, b1, nullptr, p_ha, MR, Dd, Dd, 1, 1);

    // MLP layer 2 (mode 0 -> fp32 out)
    gemm_f16_kernel<<<dim3(Dd/128, MR/128), 256, G_SMEM>>>(
        p_ha, p_w2t, b2, out, nullptr, MR, Dd, Dd, 0, 0);
}

// round 11
// speedup vs baseline: 1.0285x; 1.0285x over previous
#include <cuda_runtime.h>
#include <cuda_fp16.h>
#include <cstdint>

#define Bb 2
#define Ss 4096
#define Dd 512
#define Hh 8
#define Ee 64
#define MR (Bb*Ss)          /* 8192 */
#define NQKV (3*Hh*Ee)      /* 1536 */
#define BH (Bb*Hh)          /* 16 */

// ---------------- scratch (device globals; no allocations allowed) ----------
__device__ __half g_xa[MR*Dd];                // fp16(x)
__device__ __half g_wct[NQKV*Dd];             // fp16 QKV W^T [n][k]
__device__ float g_bcat[NQKV];
__device__ float g_bsum[Dd];
__device__ __half g_wot[Dd*Dd];               // fp16 wo^T [n][k]
__device__ __half g_w1t[Dd*Dd];               // fp16 w1^T
__device__ __half g_w2t[Dd*Dd];               // fp16 w2^T
__device__ __half g_q[BH*Ss*Ee];              // fp16, q pre-scaled
__device__ __half g_k[BH*Ss*Ee];              // fp16
__device__ __half g_vt[BH*Ee*Ss];             // fp16, [bh][e][s]
__device__ __half g_ctx[MR*Dd];               // fp16 ctx [B*S, H*E]
__device__ __half g_ya[MR*Dd];                // fp16 y
__device__ __half g_ha[MR*Dd];                // fp16 hidden

// ---------------- helpers ----------------------------------------------------
__device__ __forceinline__ uint32_t smem_u32(const void* p){
    uint32_t a;
    asm("{ .reg .u64 t; cvta.to.shared.u64 t, %1; cvt.u32.u64 %0, t; }" : "=r"(a) : "l"(p));
    return a;
}
#define LDSM4(r, a) asm volatile( \
    "ldmatrix.sync.aligned.m8n8.x4.shared.b16 {%0,%1,%2,%3}, [%4];" \
    : "=r"((r)[0]), "=r"((r)[1]), "=r"((r)[2]), "=r"((r)[3]) : "r"(a))
#define MMAF16(c, a0,a1,a2,a3, b0,b1) asm volatile( \
    "mma.sync.aligned.m16n8k16.row.col.f32.f16.f16.f32 " \
    "{%0,%1,%2,%3}, {%4,%5,%6,%7}, {%8,%9}, {%0,%1,%2,%3};" \
    : "+f"((c)[0]), "+f"((c)[1]), "+f"((c)[2]), "+f"((c)[3]) \
    : "r"(a0), "r"(a1), "r"(a2), "r"(a3), "r"(b0), "r"(b1))
#define CP16(dst, src) asm volatile( \
    "cp.async.cg.shared.global [%0], [%1], 16;" :: "r"(dst), "l"(src))
#define CP_COMMIT() asm volatile("cp.async.commit_group;" ::: "memory")

__device__ __forceinline__ uint32_t pack_f16x2(float hi, float lo){
    uint32_t d;
    asm("cvt.rn.f16x2.f32 %0, %1, %2;" : "=r"(d) : "f"(hi), "f"(lo));
    return d;
}

// ---------------- fused prep kernel ------------------------------------------
__global__ void prep_kernel(const float* __restrict__ x,
                            const float* __restrict__ wq, const float* __restrict__ wk,
                            const float* __restrict__ wv, const float* __restrict__ bq,
                            const float* __restrict__ bk, const float* __restrict__ bv,
                            const float* __restrict__ wo, const float* __restrict__ w1,
                            const float* __restrict__ w2, const float* __restrict__ bo)
{
    int i = blockIdx.x*256 + threadIdx.x;
    if (i < MR*Dd) g_xa[i] = __float2half_rn(x[i]);
    if (i < NQKV*Dd) {
        int n = i >> 9, k = i & 511;
        int proj = n >> 9, hc = n & 511, h = hc >> 6, e = hc & 63;
        const float* w = (proj==0) ? wq : (proj==1 ? wk : wv);
        g_wct[i] = __float2half_rn(w[(h*Dd + k)*Ee + e]);
    }
    if (i < Dd*Dd) {
        int n = i >> 9, k = i & 511;
        int src = k*Dd + n;
        g_wot[i] = __float2half_rn(wo[src]);
        g_w1t[i] = __float2half_rn(w1[src]);
        g_w2t[i] = __float2half_rn(w2[src]);
    }
    if (i < NQKV) {
        int proj = i >> 9, hc = i & 511;
        const float* bb = (proj==0) ? bq : (proj==1 ? bk : bv);
        g_bcat[i] = bb[hc];
    }
    if (i < Dd) {
        float s = 0.f;
        #pragma unroll
        for (int h = 0; h < Hh; h++) s += bo[h*Dd + i];
        g_bsum[i] = s;
    }
}

// ---------------- fp16 single-pass tensor GEMM (3-stage, 1 sync/iter) --------
// C[M,N] = A[M,K] @ Bt^T (Bt is [N][K] row-major, fp16).
// mode 0: fp32 out (+bias,+relu); mode 1: fp16 out; mode 2: QKV scatter.
#define GP 80                   /* 32 fp16 + 16B pad; conflict-free ldmatrix */
#define GS_B 10240
#define GS_SZ 20480
#define G_SMEM (3*GS_SZ)        /* 61440 B */

__global__ __launch_bounds__(256, 2) void gemm_f16_kernel(
    const __half* __restrict__ A, const __half* __restrict__ Bt,
    const float* __restrict__ bias,
    float* __restrict__ C, __half* __restrict__ Ct,
    int M, int N, int K, int mode, int relu)
{
    extern __shared__ char sm[];
    uint32_t sb = smem_u32(sm);
    int t = threadIdx.x, wid = t >> 5, lane = t & 31;
    int mwarp = wid >> 1, nwarp = wid & 1;
    int n0 = blockIdx.x*128, m0 = blockIdx.y*128;
    int l7 = lane & 7;
    int a_blk8 = ((lane >> 3) & 1)*8, a_cofs = ((lane >> 4) & 1)*16;
    int b_blk8 = ((lane >> 4) & 1)*8, b_cofs = ((lane >> 3) & 1)*16;

    const char* pA = (const char*)A;
    const char* pB = (const char*)Bt;

    float acc[2][8][4];
    #pragma unroll
    for (int a = 0; a < 2; a++)
        #pragma unroll
        for (int b = 0; b < 8; b++)
            #pragma unroll
            for (int c = 0; c < 4; c++) acc[a][b][c] = 0.f;

    int nk = K >> 5;

    auto stage = [&](int kb, int slot){
        uint32_t db = sb + (uint32_t)slot*GS_SZ;
        #pragma unroll
        for (int j = 0; j < 2; j++) {
            int idx = t + j*256, r = idx >> 2, u = idx & 3;
            uint32_t d = db + r*GP + u*16;
            CP16(d,        pA + ((size_t)(m0 + r)*K + kb*32 + u*8)*2);
            CP16(d + GS_B, pB + ((size_t)(n0 + r)*K + kb*32 + u*8)*2);
        }
    };

    stage(0, 0); CP_COMMIT();
    stage(1, 1); CP_COMMIT();

    for (int kb = 0; kb < nk; kb++) {
        if (kb >= nk - 2) asm volatile("cp.async.wait_group 0;" ::: "memory");
        else              asm volatile("cp.async.wait_group 1;" ::: "memory");
        __syncthreads();
        if (kb + 2 < nk) { stage(kb + 2, (kb + 2) % 3); CP_COMMIT(); }
        uint32_t s0 = sb + (uint32_t)(kb % 3)*GS_SZ;

        #pragma unroll
        for (int es = 0; es < 2; es++) {
            uint32_t af[2][4];
            #pragma unroll
            for (int mf = 0; mf < 2; mf++)
                LDSM4(af[mf], s0 + (mwarp*32 + mf*16 + l7 + a_blk8)*GP
                              + es*32 + a_cofs);
            #pragma unroll
            for (int nb = 0; nb < 4; nb++) {
                uint32_t bf4[4];
                LDSM4(bf4, s0 + GS_B + (nwarp*64 + nb*16 + l7 + b_blk8)*GP
                           + es*32 + b_cofs);
                #pragma unroll
                for (int mf = 0; mf < 2; mf++) {
                    MMAF16(acc[mf][2*nb],   af[mf][0],af[mf][1],af[mf][2],af[mf][3], bf4[0], bf4[1]);
                    MMAF16(acc[mf][2*nb+1], af[mf][0],af[mf][1],af[mf][2],af[mf][3], bf4[2], bf4[3]);
                }
            }
        }
    }

    // ---- epilogue ----
    #pragma unroll
    for (int mf = 0; mf < 2; mf++) {
        #pragma unroll
        for (int f = 0; f < 8; f++) {
            int c = n0 + nwarp*64 + (f >> 1)*16 + (f & 1)*8 + 2*(lane & 3);
            float b0 = bias[c], b1 = bias[c + 1];
            int r0 = m0 + mwarp*32 + mf*16 + (lane >> 2);
            #pragma unroll
            for (int half = 0; half < 2; half++) {
                int r = r0 + half*8;
                float v0 = acc[mf][f][2*half]     + b0;
                float v1 = acc[mf][f][2*half + 1] + b1;
                if (relu) { v0 = fmaxf(v0, 0.f); v1 = fmaxf(v1, 0.f); }
                if (mode == 0) {
                    *(float2*)&C[(size_t)r*N + c] = make_float2(v0, v1);
                } else if (mode == 1) {
                    ((uint32_t*)Ct)[((size_t)r*N + c) >> 1] = pack_f16x2(v1, v0);
                } else {
                    int n = c;
                    int proj = n >> 9, h = (n >> 6) & 7, e = n & 63;
                    int bh = (r >> 12)*Hh + h;
                    int s = r & 4095;
                    if (proj == 0) { v0 *= 0.125f; v1 *= 0.125f; }
                    if (proj < 2) {
                        __half* dst = (proj ? g_k : g_q);
                        ((uint32_t*)dst)[(((size_t)bh*Ss + s)*Ee + e) >> 1] =
                            pack_f16x2(v1, v0);
                    } else {
                        g_vt[((size_t)bh*Ee + e)*Ss + s]     = __float2half_rn(v0);
                        g_vt[((size_t)bh*Ee + e + 1)*Ss + s] = __float2half_rn(v1);
                    }
                }
            }
        }
    }
}

// ---------------- fp16 flash attention (3-stage, 1 sync/iter) ----------------
// CTA = 128 queries of one (b,h); 8 warps x 16 q-rows; 64-key tiles; occ 2.
#define QK_PITCH 144            /* 64 fp16 = 128 B + 16 pad */
#define V_PITCH  144
#define ST_K 0
#define ST_V 9216
#define ST_SZ 18432
#define ATT_SMEM (3*ST_SZ)      /* 55296 B */

__device__ __forceinline__ void att_stage(
    uint32_t sbase, const __half* kp, const __half* vp,
    size_t bh, int k0, int t)
{
    const char* sk = (const char*)(kp + (bh*Ss + k0)*Ee);
    const char* sv = (const char*)(vp + bh*(size_t)Ee*Ss + k0);
    #pragma unroll
    for (int j = 0; j < 2; j++) {
        int idx = t + j*256, r = idx >> 3, u = idx & 7;
        CP16(sbase + ST_K + r*QK_PITCH + u*16, sk + (size_t)r*128 + u*16);
        CP16(sbase + ST_V + r*V_PITCH + u*16,  sv + (size_t)r*(Ss*2) + u*16);
    }
}

__global__ __launch_bounds__(256, 2) void attn_f16_kernel(
    const __half* __restrict__ qp, const __half* __restrict__ kp,
    const __half* __restrict__ vp, __half* __restrict__ ctx)
{
    extern __shared__ char smem[];
    uint32_t sb = smem_u32(smem);
    int t = threadIdx.x, wid = t >> 5, lane = t & 31;
    int g = lane >> 2, tg = lane & 3;
    size_t bh = blockIdx.y;
    int q0 = blockIdx.x * 128;

    // ---- prologue: stage Q fp16 tile into slot 0, extract fragments --------
    {
        const char* sq = (const char*)(qp + (bh*Ss + q0)*Ee);
        #pragma unroll
        for (int j = 0; j < 4; j++) {
            int idx = t + j*256, r = idx >> 3, u = idx & 7;
            CP16(sb + r*QK_PITCH + u*16, sq + (size_t)r*128 + u*16);
        }
        CP_COMMIT();
        asm volatile("cp.async.wait_group 0;" ::: "memory");
        __syncthreads();
    }
    uint32_t qf[4][4];
    {
        int arow = wid*16 + (lane & 7) + ((lane >> 3) & 1)*8;
        int acol = ((lane >> 4) & 1)*16;
        #pragma unroll
        for (int es = 0; es < 4; es++)
            LDSM4(qf[es], sb + arow*QK_PITCH + es*32 + acol);
    }
    __syncthreads();

    att_stage(sb,         kp, vp, bh, 0,  t); CP_COMMIT();
    att_stage(sb + ST_SZ, kp, vp, bh, 64, t); CP_COMMIT();

    float o[8][4];
    #pragma unroll
    for (int i = 0; i < 8; i++)
        #pragma unroll
        for (int j = 0; j < 4; j++) o[i][j] = 0.f;
    float rs_lo = 0.f, rs_hi = 0.f;

    int l7 = lane & 7, blkr = ((lane >> 4) & 1)*8, blkc = ((lane >> 3) & 1)*16;

    for (int kt = 0; kt < 64; kt++) {
        if (kt >= 62) asm volatile("cp.async.wait_group 0;" ::: "memory");
        else          asm volatile("cp.async.wait_group 1;" ::: "memory");
        __syncthreads();
        if (kt + 2 < 64) {
            att_stage(sb + (uint32_t)((kt + 2) % 3)*ST_SZ, kp, vp,
                      bh, (kt + 2)*64, t);
            CP_COMMIT();
        }
        uint32_t sof = sb + (uint32_t)(kt % 3)*ST_SZ;

        // ---- S = Q K^T: 4 e-ksteps x 4 key16-tiles -------------------------
        float s[8][4];
        #pragma unroll
        for (int i = 0; i < 8; i++)
            #pragma unroll
            for (int j = 0; j < 4; j++) s[i][j] = 0.f;

        #pragma unroll
        for (int es = 0; es < 4; es++) {
            #pragma unroll
            for (int kg2 = 0; kg2 < 4; kg2++) {
                uint32_t kb[4];
                LDSM4(kb, sof + ST_K + (kg2*16 + blkr + l7)*QK_PITCH
                          + es*32 + blkc);
                MMAF16(s[2*kg2],   qf[es][0],qf[es][1],qf[es][2],qf[es][3], kb[0], kb[1]);
                MMAF16(s[2*kg2+1], qf[es][0],qf[es][1],qf[es][2],qf[es][3], kb[2], kb[3]);
            }
        }

        // ---- fused softmax + PV --------------------------------------------
        #pragma unroll
        for (int ks = 0; ks < 4; ks++) {
            float p0 = __expf(s[2*ks][0]),   p1 = __expf(s[2*ks][1]);
            float p2 = __expf(s[2*ks][2]),   p3 = __expf(s[2*ks][3]);
            float p4 = __expf(s[2*ks+1][0]), p5 = __expf(s[2*ks+1][1]);
            float p6 = __expf(s[2*ks+1][2]), p7 = __expf(s[2*ks+1][3]);
            rs_lo += (p0 + p1) + (p4 + p5);
            rs_hi += (p2 + p3) + (p6 + p7);
            uint32_t a0 = pack_f16x2(p1, p0);
            uint32_t a1 = pack_f16x2(p3, p2);
            uint32_t a2 = pack_f16x2(p5, p4);
            uint32_t a3 = pack_f16x2(p7, p6);

            #pragma unroll
            for (int eg2 = 0; eg2 < 4; eg2++) {
                uint32_t vb[4];
                LDSM4(vb, sof + ST_V + (eg2*16 + blkr + l7)*V_PITCH
                          + ks*32 + blkc);
                MMAF16(o[2*eg2],   a0, a1, a2, a3, vb[0], vb[1]);
                MMAF16(o[2*eg2+1], a0, a1, a2, a3, vb[2], vb[3]);
            }
        }
    }

    // ---- normalize + write ctx as fp16 pairs -------------------------------
    rs_lo += __shfl_xor_sync(0xffffffffu, rs_lo, 1);
    rs_lo += __shfl_xor_sync(0xffffffffu, rs_lo, 2);
    rs_hi += __shfl_xor_sync(0xffffffffu, rs_hi, 1);
    rs_hi += __shfl_xor_sync(0xffffffffu, rs_hi, 2);
    float inv_lo = 1.0f / rs_lo, inv_hi = 1.0f / rs_hi;

    int b = (int)(bh >> 3), h = (int)(bh & 7);
    int row0 = q0 + wid*16 + g;
    #pragma unroll
    for (int half = 0; half < 2; half++) {
        int row = row0 + half*8;
        float inv = half ? inv_hi : inv_lo;
        size_t base = ((size_t)b*Ss + row)*Dd + h*Ee;
        #pragma unroll
        for (int j = 0; j < 8; j++) {
            float v0 = o[j][2*half]     * inv;
            float v1 = o[j][2*half + 1] * inv;
            ((uint32_t*)ctx)[(base + j*8 + 2*tg) >> 1] = pack_f16x2(v1, v0);
        }
    }
}

// ---------------- launcher --------------------------------------------------
extern "C" void kernel_launch(void* const* d_in, const int* in_sizes, int n_in,
                              void* d_out, int out_size)
{
    const float* x  = (const float*)d_in[0];
    const float* wq = (const float*)d_in[1];
    const float* bq = (const float*)d_in[2];
    const float* wk = (const float*)d_in[3];
    const float* bk = (const float*)d_in[4];
    const float* wv = (const float*)d_in[5];
    const float* bv = (const float*)d_in[6];
    const float* wo = (const float*)d_in[7];
    const float* bo = (const float*)d_in[8];
    const float* w1 = (const float*)d_in[9];
    const float* b1 = (const float*)d_in[10];
    const float* w2 = (const float*)d_in[11];
    const float* b2 = (const float*)d_in[12];
    float* out = (float*)d_out;

    __half *p_xa, *p_wct, *p_wot, *p_w1t, *p_w2t;
    __half *p_q, *p_k, *p_vt, *p_ctx, *p_ya, *p_ha;
    float *p_bcat, *p_bsum;
    cudaGetSymbolAddress((void**)&p_xa,   g_xa);
    cudaGetSymbolAddress((void**)&p_wct,  g_wct);
    cudaGetSymbolAddress((void**)&p_bcat, g_bcat);
    cudaGetSymbolAddress((void**)&p_bsum, g_bsum);
    cudaGetSymbolAddress((void**)&p_wot,  g_wot);
    cudaGetSymbolAddress((void**)&p_w1t,  g_w1t);
    cudaGetSymbolAddress((void**)&p_w2t,  g_w2t);
    cudaGetSymbolAddress((void**)&p_q,    g_q);
    cudaGetSymbolAddress((void**)&p_k,    g_k);
    cudaGetSymbolAddress((void**)&p_vt,   g_vt);
    cudaGetSymbolAddress((void**)&p_ctx,  g_ctx);
    cudaGetSymbolAddress((void**)&p_ya,   g_ya);
    cudaGetSymbolAddress((void**)&p_ha,   g_ha);

    cudaFuncSetAttribute(attn_f16_kernel,
        cudaFuncAttributeMaxDynamicSharedMemorySize, ATT_SMEM);
    cudaFuncSetAttribute(gemm_f16_kernel,
        cudaFuncAttributeMaxDynamicSharedMemorySize, G_SMEM);

    // fused prep (x split, QKV W^T pack, 3x W^T, bias packs) — one launch
    prep_kernel<<<(MR*Dd + 255)/256, 256>>>(x, wq, wk, wv, bq, bk, bv,
                                            wo, w1, w2, bo);

    // QKV projection (fp16, mode 2: scatter to q/k/vt)
    gemm_f16_kernel<<<dim3(NQKV/128, MR/128), 256, G_SMEM>>>(
        p_xa, p_wct, p_bcat, nullptr, nullptr, MR, NQKV, Dd, 2, 0);

    // fp16 attention (writes ctx fp16 in [B*S, H*E])
    attn_f16_kernel<<<dim3(Ss/128, BH), 256, ATT_SMEM>>>(
        p_q, p_k, p_vt, p_ctx);

    // output projection (mode 1 -> fp16 y)
    gemm_f16_kernel<<<dim3(Dd/128, MR/128), 256, G_SMEM>>>(
        p_ctx, p_wot, p_bsum, nullptr, p_ya, MR, Dd, Dd, 1, 0);

    // MLP layer 1 + ReLU (mode 1 -> fp16 hidden)
    gemm_f16_kernel<<<dim3(Dd/128, MR/128), 256, G_SMEM>>>(
        p_ya, p_w1t, b1, nullptr, p_ha, MR, Dd, Dd, 1, 1);

    // MLP layer 2 (mode 0 -> fp32 out)
    gemm_f16_kernel<<<dim3(Dd/128, MR/128), 256, G_SMEM>>>(
        p_ha, p_w2t, b2, out, nullptr, MR, Dd, Dd, 0, 0);
}

// round 12
// speedup vs baseline: 1.0327x; 1.0040x over previous
#include <cuda_runtime.h>
#include <cuda_fp16.h>
#include <cstdint>

#define Bb 2
#define Ss 4096
#define Dd 512
#define Hh 8
#define Ee 64
#define MR (Bb*Ss)          /* 8192 */
#define NQKV (3*Hh*Ee)      /* 1536 */
#define BH (Bb*Hh)          /* 16 */

// Q pre-scale: (1/sqrt(64)) * log2(e)  -> allows raw ex2 in softmax
#define QSCALE 0.1803368801111244f

// ---------------- scratch (device globals; no allocations allowed) ----------
__device__ __half g_xa[MR*Dd];
__device__ __half g_wct[NQKV*Dd];
__device__ float g_bcat[NQKV];
__device__ float g_bsum[Dd];
__device__ __half g_wot[Dd*Dd];
__device__ __half g_w1t[Dd*Dd];
__device__ __half g_w2t[Dd*Dd];
__device__ __half g_q[BH*Ss*Ee];
__device__ __half g_k[BH*Ss*Ee];
__device__ __half g_vt[BH*Ee*Ss];
__device__ __half g_ctx[MR*Dd];
__device__ __half g_ya[MR*Dd];
__device__ __half g_ha[MR*Dd];

// ---------------- helpers ----------------------------------------------------
__device__ __forceinline__ uint32_t smem_u32(const void* p){
    uint32_t a;
    asm("{ .reg .u64 t; cvta.to.shared.u64 t, %1; cvt.u32.u64 %0, t; }" : "=r"(a) : "l"(p));
    return a;
}
#define LDSM4(r, a) asm volatile( \
    "ldmatrix.sync.aligned.m8n8.x4.shared.b16 {%0,%1,%2,%3}, [%4];" \
    : "=r"((r)[0]), "=r"((r)[1]), "=r"((r)[2]), "=r"((r)[3]) : "r"(a))
#define MMAF16(c, a0,a1,a2,a3, b0,b1) asm volatile( \
    "mma.sync.aligned.m16n8k16.row.col.f32.f16.f16.f32 " \
    "{%0,%1,%2,%3}, {%4,%5,%6,%7}, {%8,%9}, {%0,%1,%2,%3};" \
    : "+f"((c)[0]), "+f"((c)[1]), "+f"((c)[2]), "+f"((c)[3]) \
    : "r"(a0), "r"(a1), "r"(a2), "r"(a3), "r"(b0), "r"(b1))
#define CP16(dst, src) asm volatile( \
    "cp.async.cg.shared.global [%0], [%1], 16;" :: "r"(dst), "l"(src))
#define CP_COMMIT() asm volatile("cp.async.commit_group;" ::: "memory")
#define CPY4(d, s) { (d)[0]=(s)[0]; (d)[1]=(s)[1]; (d)[2]=(s)[2]; (d)[3]=(s)[3]; }

__device__ __forceinline__ uint32_t pack_f16x2(float hi, float lo){
    uint32_t d;
    asm("cvt.rn.f16x2.f32 %0, %1, %2;" : "=r"(d) : "f"(hi), "f"(lo));
    return d;
}
__device__ __forceinline__ float ex2f(float x){
    float r;
    asm("ex2.approx.f32 %0, %1;" : "=f"(r) : "f"(x));
    return r;
}

// ---------------- fused prep kernel ------------------------------------------
__global__ void prep_kernel(const float* __restrict__ x,
                            const float* __restrict__ wq, const float* __restrict__ wk,
                            const float* __restrict__ wv, const float* __restrict__ bq,
                            const float* __restrict__ bk, const float* __restrict__ bv,
                            const float* __restrict__ wo, const float* __restrict__ w1,
                            const float* __restrict__ w2, const float* __restrict__ bo)
{
    int i = blockIdx.x*256 + threadIdx.x;
    if (i < MR*Dd) g_xa[i] = __float2half_rn(x[i]);
    if (i < NQKV*Dd) {
        int n = i >> 9, k = i & 511;
        int proj = n >> 9, hc = n & 511, h = hc >> 6, e = hc & 63;
        const float* w = (proj==0) ? wq : (proj==1 ? wk : wv);
        g_wct[i] = __float2half_rn(w[(h*Dd + k)*Ee + e]);
    }
    if (i < Dd*Dd) {
        int n = i >> 9, k = i & 511;
        int src = k*Dd + n;
        g_wot[i] = __float2half_rn(wo[src]);
        g_w1t[i] = __float2half_rn(w1[src]);
        g_w2t[i] = __float2half_rn(w2[src]);
    }
    if (i < NQKV) {
        int proj = i >> 9, hc = i & 511;
        const float* bb = (proj==0) ? bq : (proj==1 ? bk : bv);
        g_bcat[i] = bb[hc];
    }
    if (i < Dd) {
        float s = 0.f;
        #pragma unroll
        for (int h = 0; h < Hh; h++) s += bo[h*Dd + i];
        g_bsum[i] = s;
    }
}

// ---------------- fp16 GEMM (3-stage, fragment-pipelined) --------------------
#define GP 80
#define GS_B 10240
#define GS_SZ 20480
#define G_SMEM (3*GS_SZ)

__global__ __launch_bounds__(256, 2) void gemm_f16_kernel(
    const __half* __restrict__ A, const __half* __restrict__ Bt,
    const float* __restrict__ bias,
    float* __restrict__ C, __half* __restrict__ Ct,
    int M, int N, int K, int mode, int relu)
{
    extern __shared__ char sm[];
    uint32_t sb = smem_u32(sm);
    int t = threadIdx.x, wid = t >> 5, lane = t & 31;
    int mwarp = wid >> 1, nwarp = wid & 1;
    int n0 = blockIdx.x*128, m0 = blockIdx.y*128;
    int l7 = lane & 7;
    int a_blk8 = ((lane >> 3) & 1)*8, a_cofs = ((lane >> 4) & 1)*16;
    int b_blk8 = ((lane >> 4) & 1)*8, b_cofs = ((lane >> 3) & 1)*16;

    const char* pA = (const char*)A;
    const char* pB = (const char*)Bt;

    float acc[2][8][4];
    #pragma unroll
    for (int a = 0; a < 2; a++)
        #pragma unroll
        for (int b = 0; b < 8; b++)
            #pragma unroll
            for (int c = 0; c < 4; c++) acc[a][b][c] = 0.f;

    int nk = K >> 5;

    auto stage = [&](int kb, int slot){
        uint32_t db = sb + (uint32_t)slot*GS_SZ;
        #pragma unroll
        for (int j = 0; j < 2; j++) {
            int idx = t + j*256, r = idx >> 2, u = idx & 3;
            uint32_t d = db + r*GP + u*16;
            CP16(d,        pA + ((size_t)(m0 + r)*K + kb*32 + u*8)*2);
            CP16(d + GS_B, pB + ((size_t)(n0 + r)*K + kb*32 + u*8)*2);
        }
    };

    stage(0, 0); CP_COMMIT();
    stage(1, 1); CP_COMMIT();

    for (int kb = 0; kb < nk; kb++) {
        if (kb >= nk - 2) asm volatile("cp.async.wait_group 0;" ::: "memory");
        else              asm volatile("cp.async.wait_group 1;" ::: "memory");
        __syncthreads();
        if (kb + 2 < nk) { stage(kb + 2, (kb + 2) % 3); CP_COMMIT(); }
        uint32_t s0 = sb + (uint32_t)(kb % 3)*GS_SZ;

        // load all 4 A fragments up front
        uint32_t af[2][2][4];
        #pragma unroll
        for (int es = 0; es < 2; es++)
            #pragma unroll
            for (int mf = 0; mf < 2; mf++)
                LDSM4(af[es][mf], s0 + (mwarp*32 + mf*16 + l7 + a_blk8)*GP
                                  + es*32 + a_cofs);
        // B fragments pipelined (distance 1)
        uint32_t bf0[4], bf1[4];
        LDSM4(bf0, s0 + GS_B + (nwarp*64 + l7 + b_blk8)*GP + b_cofs);
        #pragma unroll
        for (int i = 0; i < 8; i++) {
            int es = i >> 2, nb = i & 3;
            if (i < 7) {
                int j = i + 1, es2 = j >> 2, nb2 = j & 3;
                LDSM4(bf1, s0 + GS_B + (nwarp*64 + nb2*16 + l7 + b_blk8)*GP
                           + es2*32 + b_cofs);
            }
            #pragma unroll
            for (int mf = 0; mf < 2; mf++) {
                MMAF16(acc[mf][2*nb],   af[es][mf][0],af[es][mf][1],af[es][mf][2],af[es][mf][3], bf0[0], bf0[1]);
                MMAF16(acc[mf][2*nb+1], af[es][mf][0],af[es][mf][1],af[es][mf][2],af[es][mf][3], bf0[2], bf0[3]);
            }
            CPY4(bf0, bf1);
        }
    }

    // ---- epilogue ----
    #pragma unroll
    for (int mf = 0; mf < 2; mf++) {
        #pragma unroll
        for (int f = 0; f < 8; f++) {
            int c = n0 + nwarp*64 + (f >> 1)*16 + (f & 1)*8 + 2*(lane & 3);
            float b0 = bias[c], b1 = bias[c + 1];
            int r0 = m0 + mwarp*32 + mf*16 + (lane >> 2);
            #pragma unroll
            for (int half = 0; half < 2; half++) {
                int r = r0 + half*8;
                float v0 = acc[mf][f][2*half]     + b0;
                float v1 = acc[mf][f][2*half + 1] + b1;
                if (relu) { v0 = fmaxf(v0, 0.f); v1 = fmaxf(v1, 0.f); }
                if (mode == 0) {
                    *(float2*)&C[(size_t)r*N + c] = make_float2(v0, v1);
                } else if (mode == 1) {
                    ((uint32_t*)Ct)[((size_t)r*N + c) >> 1] = pack_f16x2(v1, v0);
                } else {
                    int n = c;
                    int proj = n >> 9, h = (n >> 6) & 7, e = n & 63;
                    int bh = (r >> 12)*Hh + h;
                    int s = r & 4095;
                    if (proj == 0) { v0 *= QSCALE; v1 *= QSCALE; }
                    if (proj < 2) {
                        __half* dst = (proj ? g_k : g_q);
                        ((uint32_t*)dst)[(((size_t)bh*Ss + s)*Ee + e) >> 1] =
                            pack_f16x2(v1, v0);
                    } else {
                        g_vt[((size_t)bh*Ee + e)*Ss + s]     = __float2half_rn(v0);
                        g_vt[((size_t)bh*Ee + e + 1)*Ss + s] = __float2half_rn(v1);
                    }
                }
            }
        }
    }
}

// ---------------- fp16 flash attention (3-stage, fragment-pipelined) ---------
#define QK_PITCH 144
#define V_PITCH  144
#define ST_K 0
#define ST_V 9216
#define ST_SZ 18432
#define ATT_SMEM (3*ST_SZ)

__device__ __forceinline__ void att_stage(
    uint32_t sbase, const __half* kp, const __half* vp,
    size_t bh, int k0, int t)
{
    const char* sk = (const char*)(kp + (bh*Ss + k0)*Ee);
    const char* sv = (const char*)(vp + bh*(size_t)Ee*Ss + k0);
    #pragma unroll
    for (int j = 0; j < 2; j++) {
        int idx = t + j*256, r = idx >> 3, u = idx & 7;
        CP16(sbase + ST_K + r*QK_PITCH + u*16, sk + (size_t)r*128 + u*16);
        CP16(sbase + ST_V + r*V_PITCH + u*16,  sv + (size_t)r*(Ss*2) + u*16);
    }
}

__global__ __launch_bounds__(256, 2) void attn_f16_kernel(
    const __half* __restrict__ qp, const __half* __restrict__ kp,
    const __half* __restrict__ vp, __half* __restrict__ ctx)
{
    extern __shared__ char smem[];
    uint32_t sb = smem_u32(smem);
    int t = threadIdx.x, wid = t >> 5, lane = t & 31;
    int g = lane >> 2, tg = lane & 3;
    size_t bh = blockIdx.y;
    int q0 = blockIdx.x * 128;

    // ---- prologue: stage Q tile into slot 0, extract fragments -------------
    {
        const char* sq = (const char*)(qp + (bh*Ss + q0)*Ee);
        #pragma unroll
        for (int j = 0; j < 4; j++) {
            int idx = t + j*256, r = idx >> 3, u = idx & 7;
            CP16(sb + r*QK_PITCH + u*16, sq + (size_t)r*128 + u*16);
        }
        CP_COMMIT();
        asm volatile("cp.async.wait_group 0;" ::: "memory");
        __syncthreads();
    }
    uint32_t qf[4][4];
    {
        int arow = wid*16 + (lane & 7) + ((lane >> 3) & 1)*8;
        int acol = ((lane >> 4) & 1)*16;
        #pragma unroll
        for (int es = 0; es < 4; es++)
            LDSM4(qf[es], sb + arow*QK_PITCH + es*32 + acol);
    }
    __syncthreads();

    att_stage(sb,         kp, vp, bh, 0,  t); CP_COMMIT();
    att_stage(sb + ST_SZ, kp, vp, bh, 64, t); CP_COMMIT();

    float o[8][4];
    #pragma unroll
    for (int i = 0; i < 8; i++)
        #pragma unroll
        for (int j = 0; j < 4; j++) o[i][j] = 0.f;
    float rs_lo = 0.f, rs_hi = 0.f;

    int l7 = lane & 7, blkr = ((lane >> 4) & 1)*8, blkc = ((lane >> 3) & 1)*16;

    for (int kt = 0; kt < 64; kt++) {
        if (kt >= 62) asm volatile("cp.async.wait_group 0;" ::: "memory");
        else          asm volatile("cp.async.wait_group 1;" ::: "memory");
        __syncthreads();
        if (kt + 2 < 64) {
            att_stage(sb + (uint32_t)((kt + 2) % 3)*ST_SZ, kp, vp,
                      bh, (kt + 2)*64, t);
            CP_COMMIT();
        }
        uint32_t sof = sb + (uint32_t)(kt % 3)*ST_SZ;

        // ---- S = Q K^T, K fragments pipelined ------------------------------
        float s[8][4];
        #pragma unroll
        for (int i = 0; i < 8; i++)
            #pragma unroll
            for (int j = 0; j < 4; j++) s[i][j] = 0.f;

        {
            uint32_t kf0[4], kf1[4];
            LDSM4(kf0, sof + ST_K + (blkr + l7)*QK_PITCH + blkc);
            #pragma unroll
            for (int i = 0; i < 16; i++) {
                int es = i >> 2, kg2 = i & 3;
                if (i < 15) {
                    int j = i + 1, es2 = j >> 2, kg2b = j & 3;
                    LDSM4(kf1, sof + ST_K + (kg2b*16 + blkr + l7)*QK_PITCH
                               + es2*32 + blkc);
                }
                MMAF16(s[2*kg2],   qf[es][0],qf[es][1],qf[es][2],qf[es][3], kf0[0], kf0[1]);
                MMAF16(s[2*kg2+1], qf[es][0],qf[es][1],qf[es][2],qf[es][3], kf0[2], kf0[3]);
                CPY4(kf0, kf1);
            }
        }

        // ---- fused softmax (raw ex2) + PV, V fragments pipelined -----------
        {
            uint32_t vf0[4], vf1[4];
            LDSM4(vf0, sof + ST_V + (blkr + l7)*V_PITCH + blkc);
            #pragma unroll
            for (int ks = 0; ks < 4; ks++) {
                float p0 = ex2f(s[2*ks][0]),   p1 = ex2f(s[2*ks][1]);
                float p2 = ex2f(s[2*ks][2]),   p3 = ex2f(s[2*ks][3]);
                float p4 = ex2f(s[2*ks+1][0]), p5 = ex2f(s[2*ks+1][1]);
                float p6 = ex2f(s[2*ks+1][2]), p7 = ex2f(s[2*ks+1][3]);
                rs_lo += (p0 + p1) + (p4 + p5);
                rs_hi += (p2 + p3) + (p6 + p7);
                uint32_t a0 = pack_f16x2(p1, p0);
                uint32_t a1 = pack_f16x2(p3, p2);
                uint32_t a2 = pack_f16x2(p5, p4);
                uint32_t a3 = pack_f16x2(p7, p6);

                #pragma unroll
                for (int eg2 = 0; eg2 < 4; eg2++) {
                    int i = ks*4 + eg2;
                    if (i < 15) {
                        int j = i + 1, ks2 = j >> 2, eg2b = j & 3;
                        LDSM4(vf1, sof + ST_V + (eg2b*16 + blkr + l7)*V_PITCH
                                   + ks2*32 + blkc);
                    }
                    MMAF16(o[2*eg2],   a0, a1, a2, a3, vf0[0], vf0[1]);
                    MMAF16(o[2*eg2+1], a0, a1, a2, a3, vf0[2], vf0[3]);
                    CPY4(vf0, vf1);
                }
            }
        }
    }

    // ---- normalize + write ctx ----------------------------------------------
    rs_lo += __shfl_xor_sync(0xffffffffu, rs_lo, 1);
    rs_lo += __shfl_xor_sync(0xffffffffu, rs_lo, 2);
    rs_hi += __shfl_xor_sync(0xffffffffu, rs_hi, 1);
    rs_hi += __shfl_xor_sync(0xffffffffu, rs_hi, 2);
    float inv_lo = 1.0f / rs_lo, inv_hi = 1.0f / rs_hi;

    int b = (int)(bh >> 3), h = (int)(bh & 7);
    int row0 = q0 + wid*16 + g;
    #pragma unroll
    for (int half = 0; half < 2; half++) {
        int row = row0 + half*8;
        float inv = half ? inv_hi : inv_lo;
        size_t base = ((size_t)b*Ss + row)*Dd + h*Ee;
        #pragma unroll
        for (int j = 0; j < 8; j++) {
            float v0 = o[j][2*half]     * inv;
            float v1 = o[j][2*half + 1] * inv;
            ((uint32_t*)ctx)[(base + j*8 + 2*tg) >> 1] = pack_f16x2(v1, v0);
        }
    }
}

// ---------------- launcher --------------------------------------------------
extern "C" void kernel_launch(void* const* d_in, const int* in_sizes, int n_in,
                              void* d_out, int out_size)
{
    const float* x  = (const float*)d_in[0];
    const float* wq = (const float*)d_in[1];
    const float* bq = (const float*)d_in[2];
    const float* wk = (const float*)d_in[3];
    const float* bk = (const float*)d_in[4];
    const float* wv = (const float*)d_in[5];
    const float* bv = (const float*)d_in[6];
    const float* wo = (const float*)d_in[7];
    const float* bo = (const float*)d_in[8];
    const float* w1 = (const float*)d_in[9];
    const float* b1 = (const float*)d_in[10];
    const float* w2 = (const float*)d_in[11];
    const float* b2 = (const float*)d_in[12];
    float* out = (float*)d_out;

    __half *p_xa, *p_wct, *p_wot, *p_w1t, *p_w2t;
    __half *p_q, *p_k, *p_vt, *p_ctx, *p_ya, *p_ha;
    float *p_bcat, *p_bsum;
    cudaGetSymbolAddress((void**)&p_xa,   g_xa);
    cudaGetSymbolAddress((void**)&p_wct,  g_wct);
    cudaGetSymbolAddress((void**)&p_bcat, g_bcat);
    cudaGetSymbolAddress((void**)&p_bsum, g_bsum);
    cudaGetSymbolAddress((void**)&p_wot,  g_wot);
    cudaGetSymbolAddress((void**)&p_w1t,  g_w1t);
    cudaGetSymbolAddress((void**)&p_w2t,  g_w2t);
    cudaGetSymbolAddress((void**)&p_q,    g_q);
    cudaGetSymbolAddress((void**)&p_k,    g_k);
    cudaGetSymbolAddress((void**)&p_vt,   g_vt);
    cudaGetSymbolAddress((void**)&p_ctx,  g_ctx);
    cudaGetSymbolAddress((void**)&p_ya,   g_ya);
    cudaGetSymbolAddress((void**)&p_ha,   g_ha);

    cudaFuncSetAttribute(attn_f16_kernel,
        cudaFuncAttributeMaxDynamicSharedMemorySize, ATT_SMEM);
    cudaFuncSetAttribute(gemm_f16_kernel,
        cudaFuncAttributeMaxDynamicSharedMemorySize, G_SMEM);

    prep_kernel<<<(MR*Dd + 255)/256, 256>>>(x, wq, wk, wv, bq, bk, bv,
                                            wo, w1, w2, bo);

    gemm_f16_kernel<<<dim3(NQKV/128, MR/128), 256, G_SMEM>>>(
        p_xa, p_wct, p_bcat, nullptr, nullptr, MR, NQKV, Dd, 2, 0);

    attn_f16_kernel<<<dim3(Ss/128, BH), 256, ATT_SMEM>>>(
        p_q, p_k, p_vt, p_ctx);

    gemm_f16_kernel<<<dim3(Dd/128, MR/128), 256, G_SMEM>>>(
        p_ctx, p_wot, p_bsum, nullptr, p_ya, MR, Dd, Dd, 1, 0);

    gemm_f16_kernel<<<dim3(Dd/128, MR/128), 256, G_SMEM>>>(
        p_ya, p_w1t, b1, nullptr, p_ha, MR, Dd, Dd, 1, 1);

    gemm_f16_kernel<<<dim3(Dd/128, MR/128), 256, G_SMEM>>>(
        p_ha, p_w2t, b2, out, nullptr, MR, Dd, Dd, 0, 0);
}